// round 13
// baseline (speedup 1.0000x reference)
#include <cuda_runtime.h>
#include <cuda_bf16.h>
#include <stdint.h>

// Shapes fixed by setup_inputs
#define BATCH   2
#define S_LEN   4096
#define EMB     1024
#define NH      16
#define HD      64
#define QKV_N   3072      // per (b,s) row: [h][q64|k64|v64] -> col = h*192 + part*64 + d
#define WRAD    256

// ---- tf32 GEMM tiling (O-proj; round-7 config) ----
#define BM 128
#define BN 128
#define BK 32
#define ASTR 36
#define BSTR 132
#define A_BYTES (128 * ASTR * 4)
#define B_BYTES (BK * BSTR * 4)
#define STG_BYTES (A_BYTES + B_BYTES)    // 35328
#define NSTAGE 3
#define GEMM_SMEM (NSTAGE * STG_BYTES)   // 105984

// ---- bf16 3-split GEMM tiling (QKV) ----
#define XK2 512                          // K/2 packed words per A row
#define AH_W 2560                        // 128 rows * 20 words (16 data + 4 pad)
#define BH_W 2176                        // 16 k2-rows * 136 words (128 data + 8 pad)
#define AH_OFF 0
#define AL_OFF AH_W
#define BH_OFF (2 * AH_W)
#define BL_OFF (2 * AH_W + BH_W)
#define STG_W (2 * AH_W + 2 * BH_W)      // 9472 words = 37888 B
#define BF16_SMEM (3 * STG_W * 4)        // 113664 B -> 2 CTAs/SM (227 KB)

// Attention tiling (unchanged)
#define AQT 128
#define AKT 64
#define ATILES 10
#define QSTR 68
#define KSTR 68
#define VSTR 72
#define QS_OFF 0
#define KB_OFF (128 * QSTR)
#define VB_OFF (KB_OFF + 2 * 64 * KSTR)
#define ASMEM ((VB_OFF + 2 * 64 * VSTR) * 4)  // 106496 B

// ---------------- scratch (no allocs allowed) ----------------
__device__ float    g_qkv[(size_t)BATCH * S_LEN * QKV_N];  // 96 MB
__device__ float    g_ctx[(size_t)BATCH * S_LEN * EMB];    // 32 MB (tf32-rounded)
__device__ float    g_wo [(size_t)EMB * EMB];              //  4 MB (tf32 Wo)
__device__ uint32_t g_xh [(size_t)BATCH * S_LEN * XK2];    // 16 MB bf16-hi x (k-pairs)
__device__ uint32_t g_xl [(size_t)BATCH * S_LEN * XK2];    // 16 MB bf16-lo x
__device__ uint32_t g_wqh[(size_t)(EMB / 2) * QKV_N];      //  6 MB bf16-hi Wqkv
__device__ uint32_t g_wql[(size_t)(EMB / 2) * QKV_N];      //  6 MB bf16-lo Wqkv

// ---------------- PTX helpers ----------------
static __device__ __forceinline__ uint32_t smem_u32(const void* p) {
    uint32_t a;
    asm("{ .reg .u64 t; cvta.to.shared.u64 t, %1; cvt.u32.u64 %0, t; }" : "=r"(a) : "l"(p));
    return a;
}
static __device__ __forceinline__ void cp_async16(uint32_t dst, const void* src) {
    asm volatile("cp.async.cg.shared.global [%0], [%1], 16;" :: "r"(dst), "l"(src) : "memory");
}
static __device__ __forceinline__ void cp_commit() {
    asm volatile("cp.async.commit_group;" ::: "memory");
}
template <int N> static __device__ __forceinline__ void cp_wait() {
    asm volatile("cp.async.wait_group %0;" :: "n"(N) : "memory");
}
static __device__ __forceinline__ void prefetch_l2(const void* p) {
    asm volatile("prefetch.global.L2 [%0];" :: "l"(p));
}
static __device__ __forceinline__ uint32_t cvt_tf32(float f) {
    uint32_t r; asm("cvt.rna.tf32.f32 %0, %1;" : "=r"(r) : "f"(f)); return r;
}
static __device__ __forceinline__ void mma_tf32(float* c, const uint32_t* a, const uint32_t* b) {
    asm("mma.sync.aligned.m16n8k8.row.col.f32.tf32.tf32.f32 "
        "{%0,%1,%2,%3}, {%4,%5,%6,%7}, {%8,%9}, {%0,%1,%2,%3};"
        : "+f"(c[0]), "+f"(c[1]), "+f"(c[2]), "+f"(c[3])
        : "r"(a[0]), "r"(a[1]), "r"(a[2]), "r"(a[3]), "r"(b[0]), "r"(b[1]));
}
static __device__ __forceinline__ void mma_bf16(float* c, const uint32_t* a, const uint32_t* b) {
    asm("mma.sync.aligned.m16n8k16.row.col.f32.bf16.bf16.f32 "
        "{%0,%1,%2,%3}, {%4,%5,%6,%7}, {%8,%9}, {%0,%1,%2,%3};"
        : "+f"(c[0]), "+f"(c[1]), "+f"(c[2]), "+f"(c[3])
        : "r"(a[0]), "r"(a[1]), "r"(a[2]), "r"(a[3]), "r"(b[0]), "r"(b[1]));
}
static __device__ __forceinline__ uint16_t bf16_bits(float x) {
    __nv_bfloat16 h = __float2bfloat16_rn(x);
    return *reinterpret_cast<uint16_t*>(&h);
}
static __device__ __forceinline__ float bf16_val(uint16_t u) {
    __nv_bfloat16 h = *reinterpret_cast<__nv_bfloat16*>(&u);
    return __bfloat162float(h);
}

// ---------------- pre-pack kernels ----------------
// x: fp32 [M][1024] -> xh/xl uint32 [M][512], word = (bf16(k even) | bf16(k odd)<<16)
__global__ void pack_x_bf16(const float* __restrict__ x,
                            uint32_t* __restrict__ xh, uint32_t* __restrict__ xl) {
    size_t i = ((size_t)blockIdx.x * 256 + threadIdx.x) * 8;   // 8 fp32 per thread
    float4 v0 = *(const float4*)(x + i);
    float4 v1 = *(const float4*)(x + i + 4);
    float v[8] = {v0.x, v0.y, v0.z, v0.w, v1.x, v1.y, v1.z, v1.w};
    uint32_t h[4], l[4];
#pragma unroll
    for (int e = 0; e < 4; e++) {
        uint16_t h0 = bf16_bits(v[2 * e]),     h1 = bf16_bits(v[2 * e + 1]);
        uint16_t l0 = bf16_bits(v[2 * e]     - bf16_val(h0));
        uint16_t l1 = bf16_bits(v[2 * e + 1] - bf16_val(h1));
        h[e] = (uint32_t)h0 | ((uint32_t)h1 << 16);
        l[e] = (uint32_t)l0 | ((uint32_t)l1 << 16);
    }
    *(uint4*)(xh + i / 2) = make_uint4(h[0], h[1], h[2], h[3]);
    *(uint4*)(xl + i / 2) = make_uint4(l[0], l[1], l[2], l[3]);
}

// W: fp32 [K][N] -> Wh/Wl uint32 [K/2][N], word = (bf16(W[2k2][n]) | bf16(W[2k2+1][n])<<16)
__global__ void pack_w_bf16(const float* __restrict__ W,
                            uint32_t* __restrict__ wh, uint32_t* __restrict__ wl, int N) {
    int tid = blockIdx.x * 256 + threadIdx.x;
    int k2 = tid / (N / 4), nq = tid % (N / 4);
    float4 r0 = *(const float4*)(W + (size_t)(2 * k2) * N + 4 * nq);
    float4 r1 = *(const float4*)(W + (size_t)(2 * k2 + 1) * N + 4 * nq);
    float a[4] = {r0.x, r0.y, r0.z, r0.w};
    float b[4] = {r1.x, r1.y, r1.z, r1.w};
    uint32_t h[4], l[4];
#pragma unroll
    for (int e = 0; e < 4; e++) {
        uint16_t h0 = bf16_bits(a[e]), h1 = bf16_bits(b[e]);
        uint16_t l0 = bf16_bits(a[e] - bf16_val(h0));
        uint16_t l1 = bf16_bits(b[e] - bf16_val(h1));
        h[e] = (uint32_t)h0 | ((uint32_t)h1 << 16);
        l[e] = (uint32_t)l0 | ((uint32_t)l1 << 16);
    }
    *(uint4*)(wh + (size_t)k2 * N + 4 * nq) = make_uint4(h[0], h[1], h[2], h[3]);
    *(uint4*)(wl + (size_t)k2 * N + 4 * nq) = make_uint4(l[0], l[1], l[2], l[3]);
}

__global__ void round_tf32_k(const float* __restrict__ src, float* __restrict__ dst) {
    size_t i = ((size_t)blockIdx.x * 256 + threadIdx.x) * 4;
    float4 v = *(const float4*)(src + i);
    uint4 u = make_uint4(cvt_tf32(v.x), cvt_tf32(v.y), cvt_tf32(v.z), cvt_tf32(v.w));
    *(uint4*)(dst + i) = u;
}

// ---------------- bf16 3-split GEMM (QKV): C = x @ Wqkv + bias ---------------
// 128x128 CTA tile, 8 warps 2(m)x4(n), warp tile 64x32, BK=32 (2 k16 chunks).
static __device__ __forceinline__ void load_stage_bf16(
    const uint32_t* Xh, const uint32_t* Xl,
    const uint32_t* Wh, const uint32_t* Wl,
    int m0, int n0, int N, int k0, uint32_t sb, int t)
{
    const int k2 = k0 >> 1;
#pragma unroll
    for (int i = 0; i < 2; i++) {          // A halves: 128 rows x 64B each
        int idx = t + 256 * i;
        int r = idx >> 2, ch = idx & 3;
        cp_async16(sb + AH_OFF * 4 + r * 80 + ch * 16,
                   Xh + (size_t)(m0 + r) * XK2 + k2 + ch * 4);
        cp_async16(sb + AL_OFF * 4 + r * 80 + ch * 16,
                   Xl + (size_t)(m0 + r) * XK2 + k2 + ch * 4);
    }
#pragma unroll
    for (int i = 0; i < 2; i++) {          // B halves: 16 k2-rows x 512B each
        int idx = t + 256 * i;
        int r = idx >> 5, ch = idx & 31;
        cp_async16(sb + BH_OFF * 4 + r * 544 + ch * 16,
                   Wh + (size_t)(k2 + r) * N + n0 + ch * 4);
        cp_async16(sb + BL_OFF * 4 + r * 544 + ch * 16,
                   Wl + (size_t)(k2 + r) * N + n0 + ch * 4);
    }
    cp_commit();
}

__global__ __launch_bounds__(256, 2) void gemm_bf16_3s(
    const uint32_t* __restrict__ Xh, const uint32_t* __restrict__ Xl,
    const uint32_t* __restrict__ Wh, const uint32_t* __restrict__ Wl,
    const float* __restrict__ bias, float* __restrict__ C,
    int M, int N, int K)
{
    extern __shared__ char smem[];
    uint32_t sbase = smem_u32(smem);
    const int t = threadIdx.x;
    const int lane = t & 31, wid = t >> 5;
    const int wm = wid & 1, wn = wid >> 1;
    const int gid = lane >> 2, tig = lane & 3;
    const int m0 = blockIdx.y * BM;
    const int n0 = blockIdx.x * BN;

    float acc[4][4][4];
#pragma unroll
    for (int i = 0; i < 4; i++)
#pragma unroll
        for (int j = 0; j < 4; j++)
#pragma unroll
            for (int c = 0; c < 4; c++) acc[i][j][c] = 0.f;

    const int NS = K / BK;                 // 32
    load_stage_bf16(Xh, Xl, Wh, Wl, m0, n0, N, 0, sbase, t);
    load_stage_bf16(Xh, Xl, Wh, Wl, m0, n0, N, BK, sbase + STG_W * 4, t);

    for (int s = 0; s < NS; s++) {
        cp_wait<1>();
        __syncthreads();
        if (s + 2 < NS)
            load_stage_bf16(Xh, Xl, Wh, Wl, m0, n0, N, (s + 2) * BK,
                            sbase + ((s + 2) % 3) * STG_W * 4, t);

        const uint32_t* St = (const uint32_t*)smem + (s % 3) * STG_W;

#pragma unroll
        for (int kx = 0; kx < 2; kx++) {
            const int kb = kx * 8;         // k2 base within stage
            uint32_t ah[4][4], bh[4][2];
#pragma unroll
            for (int i = 0; i < 4; i++) {
                int m = wm * 64 + i * 16 + gid;
                ah[i][0] = St[AH_OFF + m * 20 + kb + tig];
                ah[i][1] = St[AH_OFF + (m + 8) * 20 + kb + tig];
                ah[i][2] = St[AH_OFF + m * 20 + kb + tig + 4];
                ah[i][3] = St[AH_OFF + (m + 8) * 20 + kb + tig + 4];
            }
#pragma unroll
            for (int j = 0; j < 4; j++) {
                int n = wn * 32 + j * 8 + gid;
                bh[j][0] = St[BH_OFF + (kb + tig) * 136 + n];
                bh[j][1] = St[BH_OFF + (kb + tig + 4) * 136 + n];
            }
#pragma unroll
            for (int i = 0; i < 4; i++)
#pragma unroll
                for (int j = 0; j < 4; j++)
                    mma_bf16(acc[i][j], ah[i], bh[j]);     // hi*hi

            uint32_t bl[4][2];
#pragma unroll
            for (int j = 0; j < 4; j++) {
                int n = wn * 32 + j * 8 + gid;
                bl[j][0] = St[BL_OFF + (kb + tig) * 136 + n];
                bl[j][1] = St[BL_OFF + (kb + tig + 4) * 136 + n];
            }
#pragma unroll
            for (int i = 0; i < 4; i++)
#pragma unroll
                for (int j = 0; j < 4; j++)
                    mma_bf16(acc[i][j], ah[i], bl[j]);     // hi*lo

            uint32_t al[4][4];
#pragma unroll
            for (int i = 0; i < 4; i++) {
                int m = wm * 64 + i * 16 + gid;
                al[i][0] = St[AL_OFF + m * 20 + kb + tig];
                al[i][1] = St[AL_OFF + (m + 8) * 20 + kb + tig];
                al[i][2] = St[AL_OFF + m * 20 + kb + tig + 4];
                al[i][3] = St[AL_OFF + (m + 8) * 20 + kb + tig + 4];
            }
#pragma unroll
            for (int i = 0; i < 4; i++)
#pragma unroll
                for (int j = 0; j < 4; j++)
                    mma_bf16(acc[i][j], al[i], bh[j]);     // lo*hi
        }
    }

#pragma unroll
    for (int j = 0; j < 4; j++) {
        int n = n0 + wn * 32 + j * 8 + tig * 2;
        float2 bb = *(const float2*)(bias + n);
#pragma unroll
        for (int i = 0; i < 4; i++) {
            int m = m0 + wm * 64 + i * 16 + gid;
            *(float2*)(C + (size_t)m * N + n) =
                make_float2(acc[i][j][0] + bb.x, acc[i][j][1] + bb.y);
            *(float2*)(C + (size_t)(m + 8) * N + n) =
                make_float2(acc[i][j][2] + bb.x, acc[i][j][3] + bb.y);
        }
    }
}

// ---------------- tf32 mma.sync GEMM (O-proj; round-7 version) ---------------
static __device__ __forceinline__ void load_stage(
    const float* A, const float* B, int m0, int n0, int K, int N, int k0,
    uint32_t sb, int t)
{
#pragma unroll
    for (int i = 0; i < 4; i++) {
        int idx = t + 256 * i;
        int r = idx >> 3, ch = idx & 7;
        cp_async16(sb + r * (ASTR * 4) + ch * 16,
                   A + (size_t)(m0 + r) * K + k0 + ch * 4);
    }
#pragma unroll
    for (int i = 0; i < 4; i++) {
        int idx = t + 256 * i;
        int r = idx >> 5, ch = idx & 31;
        cp_async16(sb + A_BYTES + r * (BSTR * 4) + ch * 16,
                   B + (size_t)(k0 + r) * N + n0 + ch * 4);
    }
    cp_commit();
}

__global__ __launch_bounds__(256, 2) void gemm_tf32(
    const float* __restrict__ A, const float* __restrict__ B,
    const float* __restrict__ bias, float* __restrict__ C,
    int M, int N, int K)
{
    extern __shared__ char smem[];
    uint32_t sbase = smem_u32(smem);
    const int t = threadIdx.x;
    const int lane = t & 31, wid = t >> 5;
    const int wm = wid & 1, wn = wid >> 1;
    const int gid = lane >> 2, tig = lane & 3;
    const int m0 = blockIdx.y * BM;
    const int n0 = blockIdx.x * BN;

    float acc[4][4][4];
#pragma unroll
    for (int i = 0; i < 4; i++)
#pragma unroll
        for (int j = 0; j < 4; j++)
#pragma unroll
            for (int c = 0; c < 4; c++) acc[i][j][c] = 0.f;

    const int NS = K / BK;
    load_stage(A, B, m0, n0, K, N, 0, sbase, t);
    load_stage(A, B, m0, n0, K, N, BK, sbase + STG_BYTES, t);

    for (int s = 0; s < NS; s++) {
        cp_wait<1>();
        __syncthreads();
        if (s + 2 < NS)
            load_stage(A, B, m0, n0, K, N, (s + 2) * BK,
                       sbase + ((s + 2) % NSTAGE) * STG_BYTES, t);

        const uint32_t* As = (const uint32_t*)(smem + (s % NSTAGE) * STG_BYTES);
        const uint32_t* Bs = (const uint32_t*)(smem + (s % NSTAGE) * STG_BYTES + A_BYTES);

#pragma unroll
        for (int kk = 0; kk < BK; kk += 8) {
            uint32_t a[4][4], b[4][2];
#pragma unroll
            for (int i = 0; i < 4; i++) {
                int m = wm * 64 + i * 16 + gid;
                a[i][0] = As[m * ASTR + kk + tig];
                a[i][1] = As[(m + 8) * ASTR + kk + tig];
                a[i][2] = As[m * ASTR + kk + tig + 4];
                a[i][3] = As[(m + 8) * ASTR + kk + tig + 4];
            }
#pragma unroll
            for (int j = 0; j < 4; j++) {
                int n = wn * 32 + j * 8 + gid;
                b[j][0] = Bs[(kk + tig) * BSTR + n];
                b[j][1] = Bs[(kk + tig + 4) * BSTR + n];
            }
#pragma unroll
            for (int i = 0; i < 4; i++)
#pragma unroll
                for (int j = 0; j < 4; j++)
                    mma_tf32(acc[i][j], a[i], b[j]);
        }
    }

#pragma unroll
    for (int j = 0; j < 4; j++) {
        int n = n0 + wn * 32 + j * 8 + tig * 2;
        float2 bb = *(const float2*)(bias + n);
#pragma unroll
        for (int i = 0; i < 4; i++) {
            int m = m0 + wm * 64 + i * 16 + gid;
            *(float2*)(C + (size_t)m * N + n) =
                make_float2(acc[i][j][0] + bb.x, acc[i][j][1] + bb.y);
            *(float2*)(C + (size_t)(m + 8) * N + n) =
                make_float2(acc[i][j][2] + bb.x, acc[i][j][3] + bb.y);
        }
    }
}

// ---------------- banded sliding-window attention v2 (unchanged) ------------
static __device__ __forceinline__ void swa_load_kv(
    int b, int hh, int ks, uint32_t* sw, int pb, int t)
{
    const int kr = t >> 2, kc = (t & 3) * 16;
    const float* kp = g_qkv + ((size_t)(b * S_LEN + ks + kr) * NH + hh) * 192 + 64 + kc;
    uint32_t* kd = sw + KB_OFF + pb * (64 * KSTR) + kr * KSTR + kc;
    uint32_t* vd = sw + VB_OFF + pb * (64 * VSTR) + kr * VSTR + kc;
#pragma unroll
    for (int i = 0; i < 4; i++) {
        float4 kv = *(const float4*)(kp + 4 * i);
        float4 vv = *(const float4*)(kp + 64 + 4 * i);
        *(uint4*)(kd + 4 * i) =
            make_uint4(cvt_tf32(kv.x), cvt_tf32(kv.y), cvt_tf32(kv.z), cvt_tf32(kv.w));
        *(uint4*)(vd + 4 * i) =
            make_uint4(cvt_tf32(vv.x), cvt_tf32(vv.y), cvt_tf32(vv.z), cvt_tf32(vv.w));
    }
}

__global__ __launch_bounds__(256, 2) void swa_mma(void)
{
    extern __shared__ uint32_t sw[];
    const int t = threadIdx.x;
    const int lane = t & 31, w = t >> 5;
    const int gid = lane >> 2, tig = lane & 3;
    const int nqc = S_LEN / AQT;
    const int qc = blockIdx.x % nqc;
    const int hh = (blockIdx.x / nqc) % NH;
    const int b  = blockIdx.x / (nqc * NH);
    const int qi0 = qc * AQT;

    {
        int r = t >> 1, c0 = (t & 1) * 32;
        const float* qp = g_qkv + ((size_t)(b * S_LEN + qi0 + r) * NH + hh) * 192 + c0;
        uint32_t* qs = sw + QS_OFF + r * QSTR + c0;
#pragma unroll
        for (int i = 0; i < 8; i++) {
            float4 v = *(const float4*)(qp + 4 * i);
            *(uint4*)(qs + 4 * i) =
                make_uint4(cvt_tf32(v.x), cvt_tf32(v.y), cvt_tf32(v.z), cvt_tf32(v.w));
        }
    }

    const int kt_lo = (qi0 < WRAD) ? (WRAD - qi0) / AKT : 0;
    const int kt_hi = min(ATILES - 1, (S_LEN + WRAD - AKT - qi0) / AKT);

    float oacc[8][4];
#pragma unroll
    for (int nj = 0; nj < 8; nj++)
#pragma unroll
        for (int e = 0; e < 4; e++) oacc[nj][e] = 0.f;
    float m[2] = {-1e30f, -1e30f};
    float lp[2] = {0.f, 0.f};

    const int row0 = qi0 + w * 16 + gid;
    const uint32_t* qbase = sw + QS_OFF + (w * 16 + gid) * QSTR;

    swa_load_kv(b, hh, qi0 - WRAD + kt_lo * AKT, sw, 0, t);
    int pb = 0;

    for (int kt = kt_lo; kt <= kt_hi; kt++) {
        const int ks = qi0 - WRAD + kt * AKT;
        const bool pf = (kt < kt_hi);
        __syncthreads();

        const uint32_t* Kb = sw + KB_OFF + pb * (64 * KSTR);
        const uint32_t* Vb = sw + VB_OFF + pb * (64 * VSTR);

        float sacc[8][4];
#pragma unroll
        for (int nj = 0; nj < 8; nj++)
#pragma unroll
            for (int e = 0; e < 4; e++) sacc[nj][e] = 0.f;

#pragma unroll
        for (int kk = 0; kk < 8; kk++) {
            uint32_t a[4];
            const uint32_t* qrow = qbase + kk * 8;
            a[0] = qrow[tig];
            a[1] = qrow[8 * QSTR + tig];
            a[2] = qrow[tig + 4];
            a[3] = qrow[8 * QSTR + tig + 4];
#pragma unroll
            for (int nj = 0; nj < 8; nj++) {
                const uint32_t* krow = Kb + (nj * 8 + gid) * KSTR + kk * 8;
                uint32_t bfr[2] = {krow[tig], krow[tig + 4]};
                mma_tf32(sacc[nj], a, bfr);
            }
        }

        if (pf) {
            const int kr = t >> 2, kc = (t & 3) * 16;
            const float* np = g_qkv +
                ((size_t)(b * S_LEN + ks + AKT + kr) * NH + hh) * 192 + 64 + kc;
            prefetch_l2(np);
            prefetch_l2(np + 64);
        }

        float mt[2] = {-1e30f, -1e30f};
#pragma unroll
        for (int nj = 0; nj < 8; nj++)
#pragma unroll
            for (int e = 0; e < 4; e++) {
                int col = ks + nj * 8 + 2 * tig + (e & 1);
                int d = col - (row0 + (e >> 1) * 8);
                bool val = (d >= -WRAD) && (d <= WRAD);
                float sv = val ? sacc[nj][e] * 0.125f : -1e30f;
                sacc[nj][e] = sv;
                mt[e >> 1] = fmaxf(mt[e >> 1], sv);
            }
#pragma unroll
        for (int hE = 0; hE < 2; hE++) {
            mt[hE] = fmaxf(mt[hE], __shfl_xor_sync(0xffffffffu, mt[hE], 1));
            mt[hE] = fmaxf(mt[hE], __shfl_xor_sync(0xffffffffu, mt[hE], 2));
            float mn = fmaxf(m[hE], mt[hE]);
            float corr = __expf(m[hE] - mn);
            m[hE] = mn;
            lp[hE] *= corr;
#pragma unroll
            for (int nj = 0; nj < 8; nj++) {
                oacc[nj][2 * hE]     *= corr;
                oacc[nj][2 * hE + 1] *= corr;
            }
        }

        uint32_t pu[8][4];
#pragma unroll
        for (int nj = 0; nj < 8; nj++)
#pragma unroll
            for (int e = 0; e < 4; e++) {
                float p = (sacc[nj][e] > -1e29f)
                        ? __expf(sacc[nj][e] - m[e >> 1]) : 0.f;
                lp[e >> 1] += p;
                pu[nj][e] = cvt_tf32(p);
            }

#pragma unroll
        for (int kk = 0; kk < 8; kk++) {
            uint32_t a[4];
            int src0 = (lane & ~3) | (tig >> 1);
            int src1 = src0 | 2;
            uint32_t x00 = __shfl_sync(0xffffffffu, pu[kk][0], src0);
            uint32_t x01 = __shfl_sync(0xffffffffu, pu[kk][1], src0);
            uint32_t x02 = __shfl_sync(0xffffffffu, pu[kk][2], src0);
            uint32_t x03 = __shfl_sync(0xffffffffu, pu[kk][3], src0);
            uint32_t x10 = __shfl_sync(0xffffffffu, pu[kk][0], src1);
            uint32_t x11 = __shfl_sync(0xffffffffu, pu[kk][1], src1);
            uint32_t x12 = __shfl_sync(0xffffffffu, pu[kk][2], src1);
            uint32_t x13 = __shfl_sync(0xffffffffu, pu[kk][3], src1);
            a[0] = (tig & 1) ? x01 : x00;
            a[1] = (tig & 1) ? x03 : x02;
            a[2] = (tig & 1) ? x11 : x10;
            a[3] = (tig & 1) ? x13 : x12;
#pragma unroll
            for (int nj = 0; nj < 8; nj++) {
                const uint32_t* vrow = Vb + (kk * 8 + tig) * VSTR + nj * 8 + gid;
                uint32_t bfr[2] = {vrow[0], vrow[4 * VSTR]};
                mma_tf32(oacc[nj], a, bfr);
            }
        }

        if (pf) {
            swa_load_kv(b, hh, ks + AKT, sw, pb ^ 1, t);
            pb ^= 1;
        }
    }

    float linv[2];
#pragma unroll
    for (int hE = 0; hE < 2; hE++) {
        float l = lp[hE];
        l += __shfl_xor_sync(0xffffffffu, l, 1);
        l += __shfl_xor_sync(0xffffffffu, l, 2);
        linv[hE] = 1.0f / l;
    }
#pragma unroll
    for (int nj = 0; nj < 8; nj++) {
        int col = nj * 8 + 2 * tig;
        float* op = g_ctx + (size_t)(b * S_LEN + row0) * EMB + hh * HD + col;
        *(float2*)op = make_float2(
            __uint_as_float(cvt_tf32(oacc[nj][0] * linv[0])),
            __uint_as_float(cvt_tf32(oacc[nj][1] * linv[0])));
        *(float2*)(op + (size_t)8 * EMB) = make_float2(
            __uint_as_float(cvt_tf32(oacc[nj][2] * linv[1])),
            __uint_as_float(cvt_tf32(oacc[nj][3] * linv[1])));
    }
}

// ---------------- launch ----------------------------------------------------
extern "C" void kernel_launch(void* const* d_in, const int* in_sizes, int n_in,
                              void* d_out, int out_size) {
    const float* x    = (const float*)d_in[0];
    const float* Wqkv = (const float*)d_in[1];
    const float* bqkv = (const float*)d_in[2];
    const float* Wo   = (const float*)d_in[3];
    const float* bo   = (const float*)d_in[4];
    float* out = (float*)d_out;

    float *qkv, *ctx, *wo;
    uint32_t *xh, *xl, *wqh, *wql;
    cudaGetSymbolAddress((void**)&qkv, g_qkv);
    cudaGetSymbolAddress((void**)&ctx, g_ctx);
    cudaGetSymbolAddress((void**)&wo,  g_wo);
    cudaGetSymbolAddress((void**)&xh,  g_xh);
    cudaGetSymbolAddress((void**)&xl,  g_xl);
    cudaGetSymbolAddress((void**)&wqh, g_wqh);
    cudaGetSymbolAddress((void**)&wql, g_wql);

    const int M = BATCH * S_LEN;   // 8192

    cudaFuncSetAttribute(gemm_bf16_3s, cudaFuncAttributeMaxDynamicSharedMemorySize, BF16_SMEM);
    cudaFuncSetAttribute(gemm_tf32, cudaFuncAttributeMaxDynamicSharedMemorySize, GEMM_SMEM);
    cudaFuncSetAttribute(swa_mma, cudaFuncAttributeMaxDynamicSharedMemorySize, ASMEM);

    // pre-pack operands
    pack_x_bf16<<<(M * EMB) / (256 * 8), 256>>>(x, xh, xl);
    pack_w_bf16<<<((EMB / 2) * (QKV_N / 4)) / 256, 256>>>(Wqkv, wqh, wql, QKV_N);
    round_tf32_k<<<(EMB * EMB) / 1024, 256>>>(Wo, wo);

    // 1) QKV projection (bf16 3-split, tests bf16 HMMA rate)
    gemm_bf16_3s<<<dim3(QKV_N / BN, M / BM), 256, BF16_SMEM>>>(
        xh, xl, wqh, wql, bqkv, qkv, M, QKV_N, EMB);

    // 2) banded sliding-window attention (tf32 path, unchanged)
    swa_mma<<<BATCH * NH * (S_LEN / AQT), 256, ASMEM>>>();

    // 3) output projection (tf32 control)
    gemm_tf32<<<dim3(EMB / BN, M / BM), 256, GEMM_SMEM>>>(ctx, wo, bo, out, M, EMB, EMB);
}

// round 14
// speedup vs baseline: 2.0194x; 2.0194x over previous
#include <cuda_runtime.h>
#include <cuda_fp16.h>
#include <stdint.h>

// Shapes fixed by setup_inputs
#define BATCH   2
#define S_LEN   4096
#define EMB     1024
#define NH      16
#define HD      64
#define QKV_N   3072      // per (b,s): [h][q64|k64|v64]
#define QKV_W   1536      // packed words per row
#define WRAD    256

// ---- fp16 GEMM tiling: 128x128 CTA, 64x32 warp tile, BK=32 (2 k16 chunks) --
#define BM 128
#define BN 128
#define BK 32
#define GA_W 2560                        // A stage: 128 rows * 20 words (16+4 pad)
#define GB_W 2176                        // B stage: 16 k2-rows * 136 words (128+8)
#define GA_OFF 0
#define GB_OFF GA_W
#define GSTG_W (GA_W + GB_W)             // 4736 words = 18944 B
#define GEMM_SMEM (3 * GSTG_W * 4)       // 56832 B -> 2 CTAs/SM

// ---- attention tiling: CTA = (b,h,128q); 8 warps x 16 rows x 64 keys -------
#define AQT 128
#define AKT 64
#define ATILES 10
#define QSTR 36                          // packed words per Q row (32 + 4 pad)
#define KSTR 36
#define VSTR 36                          // Vt: 64 d-rows x (32 keypairs + 4 pad)
#define QS_OFF 0
#define KB_OFF (128 * QSTR)              // 4608
#define VB_OFF (KB_OFF + 2 * 64 * KSTR)  // 9216
#define ASMEM ((VB_OFF + 2 * 64 * VSTR) * 4)  // 55296 B -> 2 CTAs/SM

// ---------------- scratch (no allocs allowed) ----------------
__device__ uint32_t g_qkvh[(size_t)BATCH * S_LEN * QKV_W];  // 50 MB packed fp16 qkv
__device__ uint32_t g_ctxh[(size_t)BATCH * S_LEN * (EMB/2)];// 16 MB packed fp16 ctx
__device__ uint32_t g_xh  [(size_t)BATCH * S_LEN * (EMB/2)];// 16 MB packed fp16 x
__device__ uint32_t g_wqh [(size_t)(EMB/2) * QKV_N];        // 6 MB packed fp16 Wqkv
__device__ uint32_t g_woh [(size_t)(EMB/2) * EMB];          // 2 MB packed fp16 Wo

// ---------------- PTX helpers ----------------
static __device__ __forceinline__ uint32_t smem_u32(const void* p) {
    uint32_t a;
    asm("{ .reg .u64 t; cvta.to.shared.u64 t, %1; cvt.u32.u64 %0, t; }" : "=r"(a) : "l"(p));
    return a;
}
static __device__ __forceinline__ void cp_async16(uint32_t dst, const void* src) {
    asm volatile("cp.async.cg.shared.global [%0], [%1], 16;" :: "r"(dst), "l"(src) : "memory");
}
static __device__ __forceinline__ void cp_commit() {
    asm volatile("cp.async.commit_group;" ::: "memory");
}
template <int N> static __device__ __forceinline__ void cp_wait() {
    asm volatile("cp.async.wait_group %0;" :: "n"(N) : "memory");
}
static __device__ __forceinline__ void prefetch_l2(const void* p) {
    asm volatile("prefetch.global.L2 [%0];" :: "l"(p));
}
static __device__ __forceinline__ void mma_f16(float* c, const uint32_t* a, const uint32_t* b) {
    asm("mma.sync.aligned.m16n8k16.row.col.f32.f16.f16.f32 "
        "{%0,%1,%2,%3}, {%4,%5,%6,%7}, {%8,%9}, {%0,%1,%2,%3};"
        : "+f"(c[0]), "+f"(c[1]), "+f"(c[2]), "+f"(c[3])
        : "r"(a[0]), "r"(a[1]), "r"(a[2]), "r"(a[3]), "r"(b[0]), "r"(b[1]));
}
static __device__ __forceinline__ uint32_t h2(float a, float b) {
    __half2 v = __floats2half2_rn(a, b);
    return *reinterpret_cast<uint32_t*>(&v);
}

// ---------------- pack kernels ----------------
// A-side: fp32 [R][C] -> uint32 [R][C/2], word = (h(r,2c), h(r,2c+1))
__global__ void pack_a_fp16(const float* __restrict__ src, uint32_t* __restrict__ dst) {
    size_t i = ((size_t)blockIdx.x * 256 + threadIdx.x) * 8;
    float4 v0 = *(const float4*)(src + i);
    float4 v1 = *(const float4*)(src + i + 4);
    *(uint4*)(dst + i / 2) = make_uint4(
        h2(v0.x, v0.y), h2(v0.z, v0.w), h2(v1.x, v1.y), h2(v1.z, v1.w));
}
// B-side: fp32 [K][N] -> uint32 [K/2][N], word = (h(W[2k2][n]), h(W[2k2+1][n]))
__global__ void pack_b_fp16(const float* __restrict__ W, uint32_t* __restrict__ wh, int N) {
    int tid = blockIdx.x * 256 + threadIdx.x;
    int k2 = tid / (N / 4), nq = tid % (N / 4);
    float4 r0 = *(const float4*)(W + (size_t)(2 * k2) * N + 4 * nq);
    float4 r1 = *(const float4*)(W + (size_t)(2 * k2 + 1) * N + 4 * nq);
    *(uint4*)(wh + (size_t)k2 * N + 4 * nq) = make_uint4(
        h2(r0.x, r1.x), h2(r0.y, r1.y), h2(r0.z, r1.z), h2(r0.w, r1.w));
}

// ---------------- fp16 GEMM: C[M,N] = A @ B + bias --------------------------
// A packed [M][K/2] words, B packed [K/2][N] words. packout: write half2 words.
static __device__ __forceinline__ void load_stage_fp16(
    const uint32_t* Ah, const uint32_t* Bh,
    int m0, int n0, int N, int Kw, int k2, uint32_t sb, int t)
{
#pragma unroll
    for (int i = 0; i < 2; i++) {          // A: 128 rows x 64B
        int idx = t + 256 * i;
        int r = idx >> 2, ch = idx & 3;
        cp_async16(sb + GA_OFF * 4 + r * 80 + ch * 16,
                   Ah + (size_t)(m0 + r) * Kw + k2 + ch * 4);
    }
#pragma unroll
    for (int i = 0; i < 2; i++) {          // B: 16 k2-rows x 512B
        int idx = t + 256 * i;
        int r = idx >> 5, ch = idx & 31;
        cp_async16(sb + GB_OFF * 4 + r * 544 + ch * 16,
                   Bh + (size_t)(k2 + r) * N + n0 + ch * 4);
    }
    cp_commit();
}

__global__ __launch_bounds__(256, 2) void gemm_fp16(
    const uint32_t* __restrict__ Ah, const uint32_t* __restrict__ Bh,
    const float* __restrict__ bias, void* __restrict__ Cout,
    int M, int N, int K, int packout)
{
    extern __shared__ char smem[];
    uint32_t sbase = smem_u32(smem);
    const int t = threadIdx.x;
    const int lane = t & 31, wid = t >> 5;
    const int wm = wid & 1, wn = wid >> 1;
    const int gid = lane >> 2, tig = lane & 3;
    const int m0 = blockIdx.y * BM;
    const int n0 = blockIdx.x * BN;
    const int Kw = K / 2;

    float acc[4][4][4];
#pragma unroll
    for (int i = 0; i < 4; i++)
#pragma unroll
        for (int j = 0; j < 4; j++)
#pragma unroll
            for (int c = 0; c < 4; c++) acc[i][j][c] = 0.f;

    const int NS = K / BK;                 // 32
    load_stage_fp16(Ah, Bh, m0, n0, N, Kw, 0, sbase, t);
    load_stage_fp16(Ah, Bh, m0, n0, N, Kw, 16, sbase + GSTG_W * 4, t);

    for (int s = 0; s < NS; s++) {
        cp_wait<1>();
        __syncthreads();
        if (s + 2 < NS)
            load_stage_fp16(Ah, Bh, m0, n0, N, Kw, (s + 2) * 16,
                            sbase + ((s + 2) % 3) * GSTG_W * 4, t);

        const uint32_t* St = (const uint32_t*)smem + (s % 3) * GSTG_W;

#pragma unroll
        for (int kx = 0; kx < 2; kx++) {
            const int kb = kx * 8;         // k2 base within stage
            uint32_t a[4][4], b[4][2];
#pragma unroll
            for (int i = 0; i < 4; i++) {
                int m = wm * 64 + i * 16 + gid;
                a[i][0] = St[GA_OFF + m * 20 + kb + tig];
                a[i][1] = St[GA_OFF + (m + 8) * 20 + kb + tig];
                a[i][2] = St[GA_OFF + m * 20 + kb + tig + 4];
                a[i][3] = St[GA_OFF + (m + 8) * 20 + kb + tig + 4];
            }
#pragma unroll
            for (int j = 0; j < 4; j++) {
                int n = wn * 32 + j * 8 + gid;
                b[j][0] = St[GB_OFF + (kb + tig) * 136 + n];
                b[j][1] = St[GB_OFF + (kb + tig + 4) * 136 + n];
            }
#pragma unroll
            for (int i = 0; i < 4; i++)
#pragma unroll
                for (int j = 0; j < 4; j++)
                    mma_f16(acc[i][j], a[i], b[j]);
        }
    }

    if (packout) {
        uint32_t* C = (uint32_t*)Cout;
        const int Nw = N / 2;
#pragma unroll
        for (int j = 0; j < 4; j++) {
            int n = n0 + wn * 32 + j * 8 + tig * 2;
            float2 bb = *(const float2*)(bias + n);
#pragma unroll
            for (int i = 0; i < 4; i++) {
                int m = m0 + wm * 64 + i * 16 + gid;
                C[(size_t)m * Nw + n / 2] =
                    h2(acc[i][j][0] + bb.x, acc[i][j][1] + bb.y);
                C[(size_t)(m + 8) * Nw + n / 2] =
                    h2(acc[i][j][2] + bb.x, acc[i][j][3] + bb.y);
            }
        }
    } else {
        float* C = (float*)Cout;
#pragma unroll
        for (int j = 0; j < 4; j++) {
            int n = n0 + wn * 32 + j * 8 + tig * 2;
            float2 bb = *(const float2*)(bias + n);
#pragma unroll
            for (int i = 0; i < 4; i++) {
                int m = m0 + wm * 64 + i * 16 + gid;
                *(float2*)(C + (size_t)m * N + n) =
                    make_float2(acc[i][j][0] + bb.x, acc[i][j][1] + bb.y);
                *(float2*)(C + (size_t)(m + 8) * N + n) =
                    make_float2(acc[i][j][2] + bb.x, acc[i][j][3] + bb.y);
            }
        }
    }
}

// ---------------- banded sliding-window attention, fp16 ---------------------
// K copied packed (d-pairs); V transposed to key-pair words via byte_perm.
static __device__ __forceinline__ void swa_load_kv(
    int b, int hh, int ks, uint32_t* sw, int pb, int t)
{
    {   // K: 64 rows x 32 words, direct copy
        const int kr = t >> 2, kc = (t & 3) * 8;
        const uint32_t* kp = g_qkvh + (size_t)(b * S_LEN + ks + kr) * QKV_W + hh * 96 + 32 + kc;
        uint32_t* kd = sw + KB_OFF + pb * (64 * KSTR) + kr * KSTR + kc;
        *(uint4*)kd       = *(const uint4*)kp;
        *(uint4*)(kd + 4) = *(const uint4*)(kp + 4);
    }
    {   // V: transpose to Vt[d][keypair]
        const int kr2 = t & 31, dg = t >> 5;           // keypair, d-group of 8
        const uint32_t* va = g_qkvh + (size_t)(b * S_LEN + ks + 2 * kr2) * QKV_W + hh * 96 + 64 + dg * 4;
        uint4 wa = *(const uint4*)va;
        uint4 wb = *(const uint4*)(va + QKV_W);
        uint32_t* vd = sw + VB_OFF + pb * (64 * VSTR) + kr2;
        uint32_t aw[4] = {wa.x, wa.y, wa.z, wa.w};
        uint32_t bw[4] = {wb.x, wb.y, wb.z, wb.w};
#pragma unroll
        for (int j = 0; j < 4; j++) {
            int d0 = dg * 8 + 2 * j;
            vd[(size_t)d0 * VSTR]       = __byte_perm(aw[j], bw[j], 0x5410);
            vd[(size_t)(d0 + 1) * VSTR] = __byte_perm(aw[j], bw[j], 0x7632);
        }
    }
}

__global__ __launch_bounds__(256, 2) void swa_mma(void)
{
    extern __shared__ uint32_t sw[];
    const int t = threadIdx.x;
    const int lane = t & 31, w = t >> 5;
    const int gid = lane >> 2, tig = lane & 3;
    const int nqc = S_LEN / AQT;               // 32
    const int qc = blockIdx.x % nqc;
    const int hh = (blockIdx.x / nqc) % NH;
    const int b  = blockIdx.x / (nqc * NH);
    const int qi0 = qc * AQT;

    {   // Q: 128 rows x 32 words, direct copy
        int r = t >> 1, c0 = (t & 1) * 16;
        const uint32_t* qp = g_qkvh + (size_t)(b * S_LEN + qi0 + r) * QKV_W + hh * 96 + c0;
        uint32_t* qs = sw + QS_OFF + r * QSTR + c0;
        *(uint4*)qs        = *(const uint4*)qp;
        *(uint4*)(qs + 4)  = *(const uint4*)(qp + 4);
        *(uint4*)(qs + 8)  = *(const uint4*)(qp + 8);
        *(uint4*)(qs + 12) = *(const uint4*)(qp + 12);
    }

    const int kt_lo = (qi0 < WRAD) ? (WRAD - qi0) / AKT : 0;
    const int kt_hi = min(ATILES - 1, (S_LEN + WRAD - AKT - qi0) / AKT);

    float oacc[8][4];
#pragma unroll
    for (int nj = 0; nj < 8; nj++)
#pragma unroll
        for (int e = 0; e < 4; e++) oacc[nj][e] = 0.f;
    float m[2] = {-1e30f, -1e30f};
    float lp[2] = {0.f, 0.f};

    const int row0 = qi0 + w * 16 + gid;
    const uint32_t* qbase = sw + QS_OFF + (w * 16 + gid) * QSTR;

    swa_load_kv(b, hh, qi0 - WRAD + kt_lo * AKT, sw, 0, t);
    int pb = 0;

    for (int kt = kt_lo; kt <= kt_hi; kt++) {
        const int ks = qi0 - WRAD + kt * AKT;
        const bool pf = (kt < kt_hi);
        __syncthreads();

        const uint32_t* Kb = sw + KB_OFF + pb * (64 * KSTR);
        const uint32_t* Vb = sw + VB_OFF + pb * (64 * VSTR);

        // ---- S = Q @ K^T (16x64 per warp, 4 k16 chunks) ----
        float sacc[8][4];
#pragma unroll
        for (int nj = 0; nj < 8; nj++)
#pragma unroll
            for (int e = 0; e < 4; e++) sacc[nj][e] = 0.f;

#pragma unroll
        for (int c = 0; c < 4; c++) {
            uint32_t a[4];
            a[0] = qbase[c * 8 + tig];
            a[1] = qbase[8 * QSTR + c * 8 + tig];
            a[2] = qbase[c * 8 + tig + 4];
            a[3] = qbase[8 * QSTR + c * 8 + tig + 4];
#pragma unroll
            for (int nj = 0; nj < 8; nj++) {
                const uint32_t* krow = Kb + (nj * 8 + gid) * KSTR + c * 8;
                uint32_t bfr[2] = {krow[tig], krow[tig + 4]};
                mma_f16(sacc[nj], a, bfr);
            }
        }

        if (pf) {   // L2 prefetch next tile
            const uint32_t* np = g_qkvh +
                (size_t)(b * S_LEN + ks + AKT + (t >> 2)) * QKV_W + hh * 96 + 32 + (t & 3) * 16;
            prefetch_l2(np);
        }

        // ---- mask + scale + warp-local online softmax ----
        float mt[2] = {-1e30f, -1e30f};
#pragma unroll
        for (int nj = 0; nj < 8; nj++)
#pragma unroll
            for (int e = 0; e < 4; e++) {
                int col = ks + nj * 8 + 2 * tig + (e & 1);
                int d = col - (row0 + (e >> 1) * 8);
                bool val = (d >= -WRAD) && (d <= WRAD);
                float sv = val ? sacc[nj][e] * 0.125f : -1e30f;
                sacc[nj][e] = sv;
                mt[e >> 1] = fmaxf(mt[e >> 1], sv);
            }
#pragma unroll
        for (int hE = 0; hE < 2; hE++) {
            mt[hE] = fmaxf(mt[hE], __shfl_xor_sync(0xffffffffu, mt[hE], 1));
            mt[hE] = fmaxf(mt[hE], __shfl_xor_sync(0xffffffffu, mt[hE], 2));
            float mn = fmaxf(m[hE], mt[hE]);
            float corr = __expf(m[hE] - mn);
            m[hE] = mn;
            lp[hE] *= corr;
#pragma unroll
            for (int nj = 0; nj < 8; nj++) {
                oacc[nj][2 * hE]     *= corr;
                oacc[nj][2 * hE + 1] *= corr;
            }
        }

        // exp -> packed half2 P fragments (no shuffles needed: pairs are local)
        uint32_t pw[8][2];
#pragma unroll
        for (int nj = 0; nj < 8; nj++) {
            float p[4];
#pragma unroll
            for (int e = 0; e < 4; e++) {
                p[e] = (sacc[nj][e] > -1e29f)
                     ? __expf(sacc[nj][e] - m[e >> 1]) : 0.f;
                lp[e >> 1] += p[e];
            }
            pw[nj][0] = h2(p[0], p[1]);
            pw[nj][1] = h2(p[2], p[3]);
        }

        // ---- O += P @ V (A-frags from own registers) ----
#pragma unroll
        for (int c = 0; c < 4; c++) {
            uint32_t a[4] = {pw[2 * c][0], pw[2 * c][1], pw[2 * c + 1][0], pw[2 * c + 1][1]};
#pragma unroll
            for (int nj = 0; nj < 8; nj++) {
                const uint32_t* vrow = Vb + (nj * 8 + gid) * VSTR + c * 8;
                uint32_t bfr[2] = {vrow[tig], vrow[tig + 4]};
                mma_f16(oacc[nj], a, bfr);
            }
        }

        if (pf) {
            swa_load_kv(b, hh, ks + AKT, sw, pb ^ 1, t);
            pb ^= 1;
        }
    }

    // ---- finalize: quad-sum l, normalize, write packed ctx ----
    float linv[2];
#pragma unroll
    for (int hE = 0; hE < 2; hE++) {
        float l = lp[hE];
        l += __shfl_xor_sync(0xffffffffu, l, 1);
        l += __shfl_xor_sync(0xffffffffu, l, 2);
        linv[hE] = 1.0f / l;
    }
    uint32_t* cp0 = g_ctxh + (size_t)(b * S_LEN + row0) * (EMB / 2) + hh * 32;
#pragma unroll
    for (int nj = 0; nj < 8; nj++) {
        cp0[nj * 4 + tig] = h2(oacc[nj][0] * linv[0], oacc[nj][1] * linv[0]);
        cp0[(size_t)8 * (EMB / 2) + nj * 4 + tig] =
            h2(oacc[nj][2] * linv[1], oacc[nj][3] * linv[1]);
    }
}

// ---------------- launch ----------------------------------------------------
extern "C" void kernel_launch(void* const* d_in, const int* in_sizes, int n_in,
                              void* d_out, int out_size) {
    const float* x    = (const float*)d_in[0];
    const float* Wqkv = (const float*)d_in[1];
    const float* bqkv = (const float*)d_in[2];
    const float* Wo   = (const float*)d_in[3];
    const float* bo   = (const float*)d_in[4];
    float* out = (float*)d_out;

    uint32_t *qkvh, *ctxh, *xh, *wqh, *woh;
    cudaGetSymbolAddress((void**)&qkvh, g_qkvh);
    cudaGetSymbolAddress((void**)&ctxh, g_ctxh);
    cudaGetSymbolAddress((void**)&xh,   g_xh);
    cudaGetSymbolAddress((void**)&wqh,  g_wqh);
    cudaGetSymbolAddress((void**)&woh,  g_woh);

    const int M = BATCH * S_LEN;   // 8192

    cudaFuncSetAttribute(gemm_fp16, cudaFuncAttributeMaxDynamicSharedMemorySize, GEMM_SMEM);
    cudaFuncSetAttribute(swa_mma, cudaFuncAttributeMaxDynamicSharedMemorySize, ASMEM);

    // pack operands to fp16 k-pair words
    pack_a_fp16<<<(M * EMB) / (256 * 8), 256>>>(x, xh);
    pack_b_fp16<<<((EMB / 2) * (QKV_N / 4)) / 256, 256>>>(Wqkv, wqh, QKV_N);
    pack_b_fp16<<<((EMB / 2) * (EMB / 4)) / 256, 256>>>(Wo, woh, EMB);

    // 1) QKV projection (fp16, packed output)
    gemm_fp16<<<dim3(QKV_N / BN, M / BM), 256, GEMM_SMEM>>>(
        xh, wqh, bqkv, qkvh, M, QKV_N, EMB, 1);

    // 2) banded sliding-window attention (fp16)
    swa_mma<<<BATCH * NH * (S_LEN / AQT), 256, ASMEM>>>();

    // 3) output projection (fp16, fp32 output)
    gemm_fp16<<<dim3(EMB / BN, M / BM), 256, GEMM_SMEM>>>(
        ctxh, woh, bo, out, M, EMB, EMB, 0);
}

// round 15
// speedup vs baseline: 2.2104x; 1.0946x over previous
#include <cuda_runtime.h>
#include <cuda_fp16.h>
#include <stdint.h>

// Shapes fixed by setup_inputs
#define BATCH   2
#define S_LEN   4096
#define EMB     1024
#define NH      16
#define HD      64
#define QKV_N   3072      // per (b,s): [h][q64|k64|v64]
#define QKV_W   1536      // packed words per row
#define WRAD    256

// ---- fp16 GEMM tiling: 128x128 CTA, 64x32 warp tile, BK=64, ldmatrix -------
#define BM 128
#define BN 128
#define BK 64
#define SLAB_STR 36                      // words per slab row (32 data + 4 pad)
#define GA_W (128 * SLAB_STR)            // 4608 words
#define GB_W (128 * SLAB_STR)            // 4608 words (B transposed: rows = n)
#define GB_OFF GA_W
#define GSTG_W (GA_W + GB_W)             // 9216 words = 36864 B
#define GEMM_SMEM (3 * GSTG_W * 4)       // 110592 B -> 2 CTAs/SM

// ---- attention tiling (round-14, unchanged) --------------------------------
#define AQT 128
#define AKT 64
#define ATILES 10
#define QSTR 36
#define KSTR 36
#define VSTR 36
#define QS_OFF 0
#define KB_OFF (128 * QSTR)
#define VB_OFF (KB_OFF + 2 * 64 * KSTR)
#define ASMEM ((VB_OFF + 2 * 64 * VSTR) * 4)  // 55296 B

// ---------------- scratch (no allocs allowed) ----------------
__device__ uint32_t g_qkvh[(size_t)BATCH * S_LEN * QKV_W];   // 50 MB
__device__ uint32_t g_ctxh[(size_t)BATCH * S_LEN * (EMB/2)]; // 16 MB
__device__ uint32_t g_xh  [(size_t)BATCH * S_LEN * (EMB/2)]; // 16 MB
__device__ uint32_t g_wqt [(size_t)QKV_N * (EMB/2)];         // 6 MB Wqkv^T packed [N][K/2]
__device__ uint32_t g_wot [(size_t)EMB * (EMB/2)];           // 2 MB Wo^T packed [N][K/2]

// ---------------- PTX helpers ----------------
static __device__ __forceinline__ uint32_t smem_u32(const void* p) {
    uint32_t a;
    asm("{ .reg .u64 t; cvta.to.shared.u64 t, %1; cvt.u32.u64 %0, t; }" : "=r"(a) : "l"(p));
    return a;
}
static __device__ __forceinline__ void cp_async16(uint32_t dst, const void* src) {
    asm volatile("cp.async.cg.shared.global [%0], [%1], 16;" :: "r"(dst), "l"(src) : "memory");
}
static __device__ __forceinline__ void cp_commit() {
    asm volatile("cp.async.commit_group;" ::: "memory");
}
template <int N> static __device__ __forceinline__ void cp_wait() {
    asm volatile("cp.async.wait_group %0;" :: "n"(N) : "memory");
}
static __device__ __forceinline__ void prefetch_l2(const void* p) {
    asm volatile("prefetch.global.L2 [%0];" :: "l"(p));
}
static __device__ __forceinline__ void mma_f16(float* c, const uint32_t* a, const uint32_t* b) {
    asm("mma.sync.aligned.m16n8k16.row.col.f32.f16.f16.f32 "
        "{%0,%1,%2,%3}, {%4,%5,%6,%7}, {%8,%9}, {%0,%1,%2,%3};"
        : "+f"(c[0]), "+f"(c[1]), "+f"(c[2]), "+f"(c[3])
        : "r"(a[0]), "r"(a[1]), "r"(a[2]), "r"(a[3]), "r"(b[0]), "r"(b[1]));
}
static __device__ __forceinline__ void ldsm_x4(uint32_t* d, uint32_t addr) {
    asm volatile("ldmatrix.sync.aligned.m8n8.x4.shared.b16 {%0,%1,%2,%3}, [%4];"
        : "=r"(d[0]), "=r"(d[1]), "=r"(d[2]), "=r"(d[3]) : "r"(addr));
}
static __device__ __forceinline__ uint32_t h2(float a, float b) {
    __half2 v = __floats2half2_rn(a, b);
    return *reinterpret_cast<uint32_t*>(&v);
}

// ---------------- pack kernels ----------------
// A-side: fp32 [R][C] -> uint32 [R][C/2]
__global__ void pack_a_fp16(const float* __restrict__ src, uint32_t* __restrict__ dst) {
    size_t i = ((size_t)blockIdx.x * 256 + threadIdx.x) * 8;
    float4 v0 = *(const float4*)(src + i);
    float4 v1 = *(const float4*)(src + i + 4);
    *(uint4*)(dst + i / 2) = make_uint4(
        h2(v0.x, v0.y), h2(v0.z, v0.w), h2(v1.x, v1.y), h2(v1.z, v1.w));
}
// B transposed pack: fp32 W[K][N] -> wt uint32 [N][K/2], word=(h(W[2k][n]),h(W[2k+1][n]))
__global__ void pack_bt_fp16(const float* __restrict__ W, uint32_t* __restrict__ wt,
                             int N, int K) {
    __shared__ uint32_t s[32][9];
    int n0 = blockIdx.x * 32, k20 = blockIdx.y * 8;
    int tx = threadIdx.x & 31, ty = threadIdx.x >> 5;      // tx = n, ty = k2
    float a = W[(size_t)(2 * (k20 + ty)) * N + n0 + tx];
    float b = W[(size_t)(2 * (k20 + ty) + 1) * N + n0 + tx];
    s[tx][ty] = h2(a, b);
    __syncthreads();
    int n = threadIdx.x >> 3, kc = threadIdx.x & 7;
    wt[(size_t)(n0 + n) * (K / 2) + k20 + kc] = s[n][kc];
}

// ---------------- fp16 GEMM: C[M,N] = A @ B + bias --------------------------
// A packed [M][K/2], Bt packed [N][K/2]. ldmatrix fragments, BK=64.
static __device__ __forceinline__ void load_stage_fp16(
    const uint32_t* Ah, const uint32_t* Bt,
    int m0, int n0, int Kw, int k2, uint32_t sb, int t)
{
#pragma unroll
    for (int i = 0; i < 4; i++) {          // A slab: 128 rows x 128B
        int idx = t + 256 * i;
        int r = idx >> 3, ch = idx & 7;
        cp_async16(sb + (r * SLAB_STR + ch * 4) * 4,
                   Ah + (size_t)(m0 + r) * Kw + k2 + ch * 4);
    }
#pragma unroll
    for (int i = 0; i < 4; i++) {          // B slab: 128 n-rows x 128B
        int idx = t + 256 * i;
        int r = idx >> 3, ch = idx & 7;
        cp_async16(sb + (GB_OFF + r * SLAB_STR + ch * 4) * 4,
                   Bt + (size_t)(n0 + r) * Kw + k2 + ch * 4);
    }
    cp_commit();
}

__global__ __launch_bounds__(256, 2) void gemm_fp16(
    const uint32_t* __restrict__ Ah, const uint32_t* __restrict__ Bt,
    const float* __restrict__ bias, void* __restrict__ Cout,
    int M, int N, int K, int packout)
{
    extern __shared__ char smem[];
    uint32_t sbase = smem_u32(smem);
    const int t = threadIdx.x;
    const int lane = t & 31, wid = t >> 5;
    const int wm = wid & 1, wn = wid >> 1;
    const int gid = lane >> 2, tig = lane & 3;
    const int m0 = blockIdx.y * BM;
    const int n0 = blockIdx.x * BN;
    const int Kw = K / 2;

    // per-lane ldmatrix byte offsets (exclude stage base and chunk offset)
    const int l7 = lane & 7;
    uint32_t a_off[4], b_off[2];
#pragma unroll
    for (int i = 0; i < 4; i++)
        a_off[i] = ((wm * 64 + i * 16 + ((lane >> 3) & 1) * 8 + l7) * SLAB_STR
                    + (lane >> 4) * 4) * 4;
#pragma unroll
    for (int jp = 0; jp < 2; jp++)
        b_off[jp] = (GB_OFF + (wn * 32 + jp * 16 + (lane >> 4) * 8 + l7) * SLAB_STR
                     + ((lane >> 3) & 1) * 4) * 4;

    float acc[4][4][4];
#pragma unroll
    for (int i = 0; i < 4; i++)
#pragma unroll
        for (int j = 0; j < 4; j++)
#pragma unroll
            for (int c = 0; c < 4; c++) acc[i][j][c] = 0.f;

    const int NS = K / BK;                 // 16
    load_stage_fp16(Ah, Bt, m0, n0, Kw, 0, sbase, t);
    load_stage_fp16(Ah, Bt, m0, n0, Kw, 32, sbase + GSTG_W * 4, t);

    for (int s = 0; s < NS; s++) {
        cp_wait<1>();
        __syncthreads();
        if (s + 2 < NS)
            load_stage_fp16(Ah, Bt, m0, n0, Kw, (s + 2) * 32,
                            sbase + ((s + 2) % 3) * GSTG_W * 4, t);

        const uint32_t stg = sbase + (s % 3) * GSTG_W * 4;

#pragma unroll
        for (int c = 0; c < 4; c++) {      // 4 k16 chunks per stage
            const uint32_t kb4 = c * 32;   // 8 words = 32 bytes
            uint32_t a[4][4], b[4][2];
#pragma unroll
            for (int i = 0; i < 4; i++)
                ldsm_x4(a[i], stg + a_off[i] + kb4);
            {
                uint32_t d[4];
                ldsm_x4(d, stg + b_off[0] + kb4);
                b[0][0] = d[0]; b[0][1] = d[1]; b[1][0] = d[2]; b[1][1] = d[3];
                ldsm_x4(d, stg + b_off[1] + kb4);
                b[2][0] = d[0]; b[2][1] = d[1]; b[3][0] = d[2]; b[3][1] = d[3];
            }
#pragma unroll
            for (int i = 0; i < 4; i++)
#pragma unroll
                for (int j = 0; j < 4; j++)
                    mma_f16(acc[i][j], a[i], b[j]);
        }
    }

    if (packout) {
        uint32_t* C = (uint32_t*)Cout;
        const int Nw = N / 2;
#pragma unroll
        for (int j = 0; j < 4; j++) {
            int n = n0 + wn * 32 + j * 8 + tig * 2;
            float2 bb = *(const float2*)(bias + n);
#pragma unroll
            for (int i = 0; i < 4; i++) {
                int m = m0 + wm * 64 + i * 16 + gid;
                C[(size_t)m * Nw + n / 2] =
                    h2(acc[i][j][0] + bb.x, acc[i][j][1] + bb.y);
                C[(size_t)(m + 8) * Nw + n / 2] =
                    h2(acc[i][j][2] + bb.x, acc[i][j][3] + bb.y);
            }
        }
    } else {
        float* C = (float*)Cout;
#pragma unroll
        for (int j = 0; j < 4; j++) {
            int n = n0 + wn * 32 + j * 8 + tig * 2;
            float2 bb = *(const float2*)(bias + n);
#pragma unroll
            for (int i = 0; i < 4; i++) {
                int m = m0 + wm * 64 + i * 16 + gid;
                *(float2*)(C + (size_t)m * N + n) =
                    make_float2(acc[i][j][0] + bb.x, acc[i][j][1] + bb.y);
                *(float2*)(C + (size_t)(m + 8) * N + n) =
                    make_float2(acc[i][j][2] + bb.x, acc[i][j][3] + bb.y);
            }
        }
    }
}

// ---------------- banded sliding-window attention, fp16 (round-14) ----------
static __device__ __forceinline__ void swa_load_kv(
    int b, int hh, int ks, uint32_t* sw, int pb, int t)
{
    {   // K: 64 rows x 32 words, direct copy
        const int kr = t >> 2, kc = (t & 3) * 8;
        const uint32_t* kp = g_qkvh + (size_t)(b * S_LEN + ks + kr) * QKV_W + hh * 96 + 32 + kc;
        uint32_t* kd = sw + KB_OFF + pb * (64 * KSTR) + kr * KSTR + kc;
        *(uint4*)kd       = *(const uint4*)kp;
        *(uint4*)(kd + 4) = *(const uint4*)(kp + 4);
    }
    {   // V: transpose to Vt[d][keypair]
        const int kr2 = t & 31, dg = t >> 5;
        const uint32_t* va = g_qkvh + (size_t)(b * S_LEN + ks + 2 * kr2) * QKV_W + hh * 96 + 64 + dg * 4;
        uint4 wa = *(const uint4*)va;
        uint4 wb = *(const uint4*)(va + QKV_W);
        uint32_t* vd = sw + VB_OFF + pb * (64 * VSTR) + kr2;
        uint32_t aw[4] = {wa.x, wa.y, wa.z, wa.w};
        uint32_t bw[4] = {wb.x, wb.y, wb.z, wb.w};
#pragma unroll
        for (int j = 0; j < 4; j++) {
            int d0 = dg * 8 + 2 * j;
            vd[(size_t)d0 * VSTR]       = __byte_perm(aw[j], bw[j], 0x5410);
            vd[(size_t)(d0 + 1) * VSTR] = __byte_perm(aw[j], bw[j], 0x7632);
        }
    }
}

__global__ __launch_bounds__(256, 2) void swa_mma(void)
{
    extern __shared__ uint32_t sw[];
    const int t = threadIdx.x;
    const int lane = t & 31, w = t >> 5;
    const int gid = lane >> 2, tig = lane & 3;
    const int nqc = S_LEN / AQT;
    const int qc = blockIdx.x % nqc;
    const int hh = (blockIdx.x / nqc) % NH;
    const int b  = blockIdx.x / (nqc * NH);
    const int qi0 = qc * AQT;

    {
        int r = t >> 1, c0 = (t & 1) * 16;
        const uint32_t* qp = g_qkvh + (size_t)(b * S_LEN + qi0 + r) * QKV_W + hh * 96 + c0;
        uint32_t* qs = sw + QS_OFF + r * QSTR + c0;
        *(uint4*)qs        = *(const uint4*)qp;
        *(uint4*)(qs + 4)  = *(const uint4*)(qp + 4);
        *(uint4*)(qs + 8)  = *(const uint4*)(qp + 8);
        *(uint4*)(qs + 12) = *(const uint4*)(qp + 12);
    }

    const int kt_lo = (qi0 < WRAD) ? (WRAD - qi0) / AKT : 0;
    const int kt_hi = min(ATILES - 1, (S_LEN + WRAD - AKT - qi0) / AKT);

    float oacc[8][4];
#pragma unroll
    for (int nj = 0; nj < 8; nj++)
#pragma unroll
        for (int e = 0; e < 4; e++) oacc[nj][e] = 0.f;
    float m[2] = {-1e30f, -1e30f};
    float lp[2] = {0.f, 0.f};

    const int row0 = qi0 + w * 16 + gid;
    const uint32_t* qbase = sw + QS_OFF + (w * 16 + gid) * QSTR;

    swa_load_kv(b, hh, qi0 - WRAD + kt_lo * AKT, sw, 0, t);
    int pb = 0;

    for (int kt = kt_lo; kt <= kt_hi; kt++) {
        const int ks = qi0 - WRAD + kt * AKT;
        const bool pf = (kt < kt_hi);
        __syncthreads();

        const uint32_t* Kb = sw + KB_OFF + pb * (64 * KSTR);
        const uint32_t* Vb = sw + VB_OFF + pb * (64 * VSTR);

        float sacc[8][4];
#pragma unroll
        for (int nj = 0; nj < 8; nj++)
#pragma unroll
            for (int e = 0; e < 4; e++) sacc[nj][e] = 0.f;

#pragma unroll
        for (int c = 0; c < 4; c++) {
            uint32_t a[4];
            a[0] = qbase[c * 8 + tig];
            a[1] = qbase[8 * QSTR + c * 8 + tig];
            a[2] = qbase[c * 8 + tig + 4];
            a[3] = qbase[8 * QSTR + c * 8 + tig + 4];
#pragma unroll
            for (int nj = 0; nj < 8; nj++) {
                const uint32_t* krow = Kb + (nj * 8 + gid) * KSTR + c * 8;
                uint32_t bfr[2] = {krow[tig], krow[tig + 4]};
                mma_f16(sacc[nj], a, bfr);
            }
        }

        if (pf) {
            const uint32_t* np = g_qkvh +
                (size_t)(b * S_LEN + ks + AKT + (t >> 2)) * QKV_W + hh * 96 + 32 + (t & 3) * 16;
            prefetch_l2(np);
        }

        float mt[2] = {-1e30f, -1e30f};
#pragma unroll
        for (int nj = 0; nj < 8; nj++)
#pragma unroll
            for (int e = 0; e < 4; e++) {
                int col = ks + nj * 8 + 2 * tig + (e & 1);
                int d = col - (row0 + (e >> 1) * 8);
                bool val = (d >= -WRAD) && (d <= WRAD);
                float sv = val ? sacc[nj][e] * 0.125f : -1e30f;
                sacc[nj][e] = sv;
                mt[e >> 1] = fmaxf(mt[e >> 1], sv);
            }
#pragma unroll
        for (int hE = 0; hE < 2; hE++) {
            mt[hE] = fmaxf(mt[hE], __shfl_xor_sync(0xffffffffu, mt[hE], 1));
            mt[hE] = fmaxf(mt[hE], __shfl_xor_sync(0xffffffffu, mt[hE], 2));
            float mn = fmaxf(m[hE], mt[hE]);
            float corr = __expf(m[hE] - mn);
            m[hE] = mn;
            lp[hE] *= corr;
#pragma unroll
            for (int nj = 0; nj < 8; nj++) {
                oacc[nj][2 * hE]     *= corr;
                oacc[nj][2 * hE + 1] *= corr;
            }
        }

        uint32_t pw[8][2];
#pragma unroll
        for (int nj = 0; nj < 8; nj++) {
            float p[4];
#pragma unroll
            for (int e = 0; e < 4; e++) {
                p[e] = (sacc[nj][e] > -1e29f)
                     ? __expf(sacc[nj][e] - m[e >> 1]) : 0.f;
                lp[e >> 1] += p[e];
            }
            pw[nj][0] = h2(p[0], p[1]);
            pw[nj][1] = h2(p[2], p[3]);
        }

#pragma unroll
        for (int c = 0; c < 4; c++) {
            uint32_t a[4] = {pw[2 * c][0], pw[2 * c][1], pw[2 * c + 1][0], pw[2 * c + 1][1]};
#pragma unroll
            for (int nj = 0; nj < 8; nj++) {
                const uint32_t* vrow = Vb + (nj * 8 + gid) * VSTR + c * 8;
                uint32_t bfr[2] = {vrow[tig], vrow[tig + 4]};
                mma_f16(oacc[nj], a, bfr);
            }
        }

        if (pf) {
            swa_load_kv(b, hh, ks + AKT, sw, pb ^ 1, t);
            pb ^= 1;
        }
    }

    float linv[2];
#pragma unroll
    for (int hE = 0; hE < 2; hE++) {
        float l = lp[hE];
        l += __shfl_xor_sync(0xffffffffu, l, 1);
        l += __shfl_xor_sync(0xffffffffu, l, 2);
        linv[hE] = 1.0f / l;
    }
    uint32_t* cp0 = g_ctxh + (size_t)(b * S_LEN + row0) * (EMB / 2) + hh * 32;
#pragma unroll
    for (int nj = 0; nj < 8; nj++) {
        cp0[nj * 4 + tig] = h2(oacc[nj][0] * linv[0], oacc[nj][1] * linv[0]);
        cp0[(size_t)8 * (EMB / 2) + nj * 4 + tig] =
            h2(oacc[nj][2] * linv[1], oacc[nj][3] * linv[1]);
    }
}

// ---------------- launch ----------------------------------------------------
extern "C" void kernel_launch(void* const* d_in, const int* in_sizes, int n_in,
                              void* d_out, int out_size) {
    const float* x    = (const float*)d_in[0];
    const float* Wqkv = (const float*)d_in[1];
    const float* bqkv = (const float*)d_in[2];
    const float* Wo   = (const float*)d_in[3];
    const float* bo   = (const float*)d_in[4];
    float* out = (float*)d_out;

    uint32_t *qkvh, *ctxh, *xh, *wqt, *wot;
    cudaGetSymbolAddress((void**)&qkvh, g_qkvh);
    cudaGetSymbolAddress((void**)&ctxh, g_ctxh);
    cudaGetSymbolAddress((void**)&xh,   g_xh);
    cudaGetSymbolAddress((void**)&wqt,  g_wqt);
    cudaGetSymbolAddress((void**)&wot,  g_wot);

    const int M = BATCH * S_LEN;   // 8192

    cudaFuncSetAttribute(gemm_fp16, cudaFuncAttributeMaxDynamicSharedMemorySize, GEMM_SMEM);
    cudaFuncSetAttribute(swa_mma, cudaFuncAttributeMaxDynamicSharedMemorySize, ASMEM);

    // pack operands
    pack_a_fp16<<<(M * EMB) / (256 * 8), 256>>>(x, xh);
    pack_bt_fp16<<<dim3(QKV_N / 32, (EMB / 2) / 8), 256>>>(Wqkv, wqt, QKV_N, EMB);
    pack_bt_fp16<<<dim3(EMB / 32, (EMB / 2) / 8), 256>>>(Wo, wot, EMB, EMB);

    // 1) QKV projection (fp16 ldmatrix, packed output)
    gemm_fp16<<<dim3(QKV_N / BN, M / BM), 256, GEMM_SMEM>>>(
        xh, wqt, bqkv, qkvh, M, QKV_N, EMB, 1);

    // 2) banded sliding-window attention (fp16)
    swa_mma<<<BATCH * NH * (S_LEN / AQT), 256, ASMEM>>>();

    // 3) output projection (fp16 ldmatrix, fp32 output)
    gemm_fp16<<<dim3(EMB / BN, M / BM), 256, GEMM_SMEM>>>(
        ctxh, wot, bo, out, M, EMB, EMB, 0);
}

// round 16
// speedup vs baseline: 2.2568x; 1.0210x over previous
#include <cuda_runtime.h>
#include <cuda_fp16.h>
#include <stdint.h>

// Shapes fixed by setup_inputs
#define BATCH   2
#define S_LEN   4096
#define EMB     1024
#define NH      16
#define HD      64
#define QKV_N   3072      // per (b,s): [h][q64|k64|v64]
#define QKV_W   1536      // packed words per row
#define WRAD    256

// ---- fp16 GEMM tiling: 128x128 CTA, 64x32 warp tile, BK=64, ldmatrix -------
#define BM 128
#define BN 128
#define BK 64
#define SLAB_STR 36
#define GA_W (128 * SLAB_STR)
#define GB_W (128 * SLAB_STR)
#define GB_OFF GA_W
#define GSTG_W (GA_W + GB_W)             // 9216 words
#define GEMM_SMEM (3 * GSTG_W * 4)       // 110592 B -> 2 CTAs/SM

// ---- attention tiling ------------------------------------------------------
#define AQT 128
#define AKT 64
#define ATILES 10
#define QSTR 36
#define KSTR 36
#define VSTR 36
#define QS_OFF 0
#define KB_OFF (128 * QSTR)
#define VB_OFF (KB_OFF + 2 * 64 * KSTR)
#define ASMEM ((VB_OFF + 2 * 64 * VSTR) * 4)  // 55296 B
#define SCALE_LOG2E 0.1803368801111204f        // 0.125 * log2(e)

// ---------------- scratch (no allocs allowed) ----------------
__device__ uint32_t g_qkvh[(size_t)BATCH * S_LEN * QKV_W];
__device__ uint32_t g_ctxh[(size_t)BATCH * S_LEN * (EMB/2)];
__device__ uint32_t g_xh  [(size_t)BATCH * S_LEN * (EMB/2)];
__device__ uint32_t g_wqt [(size_t)QKV_N * (EMB/2)];
__device__ uint32_t g_wot [(size_t)EMB * (EMB/2)];

// ---------------- PTX helpers ----------------
static __device__ __forceinline__ uint32_t smem_u32(const void* p) {
    uint32_t a;
    asm("{ .reg .u64 t; cvta.to.shared.u64 t, %1; cvt.u32.u64 %0, t; }" : "=r"(a) : "l"(p));
    return a;
}
static __device__ __forceinline__ void cp_async16(uint32_t dst, const void* src) {
    asm volatile("cp.async.cg.shared.global [%0], [%1], 16;" :: "r"(dst), "l"(src) : "memory");
}
static __device__ __forceinline__ void cp_commit() {
    asm volatile("cp.async.commit_group;" ::: "memory");
}
template <int N> static __device__ __forceinline__ void cp_wait() {
    asm volatile("cp.async.wait_group %0;" :: "n"(N) : "memory");
}
static __device__ __forceinline__ void prefetch_l2(const void* p) {
    asm volatile("prefetch.global.L2 [%0];" :: "l"(p));
}
static __device__ __forceinline__ void mma_f16(float* c, const uint32_t* a, const uint32_t* b) {
    asm("mma.sync.aligned.m16n8k16.row.col.f32.f16.f16.f32 "
        "{%0,%1,%2,%3}, {%4,%5,%6,%7}, {%8,%9}, {%0,%1,%2,%3};"
        : "+f"(c[0]), "+f"(c[1]), "+f"(c[2]), "+f"(c[3])
        : "r"(a[0]), "r"(a[1]), "r"(a[2]), "r"(a[3]), "r"(b[0]), "r"(b[1]));
}
static __device__ __forceinline__ void ldsm_x4(uint32_t* d, uint32_t addr) {
    asm volatile("ldmatrix.sync.aligned.m8n8.x4.shared.b16 {%0,%1,%2,%3}, [%4];"
        : "=r"(d[0]), "=r"(d[1]), "=r"(d[2]), "=r"(d[3]) : "r"(addr));
}
static __device__ __forceinline__ uint32_t h2(float a, float b) {
    __half2 v = __floats2half2_rn(a, b);
    return *reinterpret_cast<uint32_t*>(&v);
}
// FMA-pipe exp2 (frees MUFU): round-to-int split + deg-4 Taylor, rel err ~4e-5.
static __device__ __forceinline__ float fast_exp2(float f) {
    f = fmaxf(f, -80.0f);
    float t = f + 12582912.0f;              // round-to-nearest-int trick
    float i = t - 12582912.0f;
    float fr = f - i;                       // [-0.5, 0.5]
    float p = 0.0096181291f;
    p = fmaf(p, fr, 0.0555041087f);
    p = fmaf(p, fr, 0.2402265070f);
    p = fmaf(p, fr, 0.6931471806f);
    p = fmaf(p, fr, 1.0f);
    int ii = (int)i;
    return __int_as_float(__float_as_int(p) + (ii << 23));
}

// ---------------- pack kernels ----------------
__global__ void pack_a_fp16(const float* __restrict__ src, uint32_t* __restrict__ dst) {
    size_t i = ((size_t)blockIdx.x * 256 + threadIdx.x) * 8;
    float4 v0 = *(const float4*)(src + i);
    float4 v1 = *(const float4*)(src + i + 4);
    *(uint4*)(dst + i / 2) = make_uint4(
        h2(v0.x, v0.y), h2(v0.z, v0.w), h2(v1.x, v1.y), h2(v1.z, v1.w));
}
__global__ void pack_bt_fp16(const float* __restrict__ W, uint32_t* __restrict__ wt,
                             int N, int K) {
    __shared__ uint32_t s[32][9];
    int n0 = blockIdx.x * 32, k20 = blockIdx.y * 8;
    int tx = threadIdx.x & 31, ty = threadIdx.x >> 5;
    float a = W[(size_t)(2 * (k20 + ty)) * N + n0 + tx];
    float b = W[(size_t)(2 * (k20 + ty) + 1) * N + n0 + tx];
    s[tx][ty] = h2(a, b);
    __syncthreads();
    int n = threadIdx.x >> 3, kc = threadIdx.x & 7;
    wt[(size_t)(n0 + n) * (K / 2) + k20 + kc] = s[n][kc];
}

// ---------------- fp16 GEMM (round-15, unchanged) ---------------------------
static __device__ __forceinline__ void load_stage_fp16(
    const uint32_t* Ah, const uint32_t* Bt,
    int m0, int n0, int Kw, int k2, uint32_t sb, int t)
{
#pragma unroll
    for (int i = 0; i < 4; i++) {
        int idx = t + 256 * i;
        int r = idx >> 3, ch = idx & 7;
        cp_async16(sb + (r * SLAB_STR + ch * 4) * 4,
                   Ah + (size_t)(m0 + r) * Kw + k2 + ch * 4);
    }
#pragma unroll
    for (int i = 0; i < 4; i++) {
        int idx = t + 256 * i;
        int r = idx >> 3, ch = idx & 7;
        cp_async16(sb + (GB_OFF + r * SLAB_STR + ch * 4) * 4,
                   Bt + (size_t)(n0 + r) * Kw + k2 + ch * 4);
    }
    cp_commit();
}

__global__ __launch_bounds__(256, 2) void gemm_fp16(
    const uint32_t* __restrict__ Ah, const uint32_t* __restrict__ Bt,
    const float* __restrict__ bias, void* __restrict__ Cout,
    int M, int N, int K, int packout)
{
    extern __shared__ char smem[];
    uint32_t sbase = smem_u32(smem);
    const int t = threadIdx.x;
    const int lane = t & 31, wid = t >> 5;
    const int wm = wid & 1, wn = wid >> 1;
    const int gid = lane >> 2, tig = lane & 3;
    const int m0 = blockIdx.y * BM;
    const int n0 = blockIdx.x * BN;
    const int Kw = K / 2;

    const int l7 = lane & 7;
    uint32_t a_off[4], b_off[2];
#pragma unroll
    for (int i = 0; i < 4; i++)
        a_off[i] = ((wm * 64 + i * 16 + ((lane >> 3) & 1) * 8 + l7) * SLAB_STR
                    + (lane >> 4) * 4) * 4;
#pragma unroll
    for (int jp = 0; jp < 2; jp++)
        b_off[jp] = (GB_OFF + (wn * 32 + jp * 16 + (lane >> 4) * 8 + l7) * SLAB_STR
                     + ((lane >> 3) & 1) * 4) * 4;

    float acc[4][4][4];
#pragma unroll
    for (int i = 0; i < 4; i++)
#pragma unroll
        for (int j = 0; j < 4; j++)
#pragma unroll
            for (int c = 0; c < 4; c++) acc[i][j][c] = 0.f;

    const int NS = K / BK;
    load_stage_fp16(Ah, Bt, m0, n0, Kw, 0, sbase, t);
    load_stage_fp16(Ah, Bt, m0, n0, Kw, 32, sbase + GSTG_W * 4, t);

    for (int s = 0; s < NS; s++) {
        cp_wait<1>();
        __syncthreads();
        if (s + 2 < NS)
            load_stage_fp16(Ah, Bt, m0, n0, Kw, (s + 2) * 32,
                            sbase + ((s + 2) % 3) * GSTG_W * 4, t);

        const uint32_t stg = sbase + (s % 3) * GSTG_W * 4;

#pragma unroll
        for (int c = 0; c < 4; c++) {
            const uint32_t kb4 = c * 32;
            uint32_t a[4][4], b[4][2];
#pragma unroll
            for (int i = 0; i < 4; i++)
                ldsm_x4(a[i], stg + a_off[i] + kb4);
            {
                uint32_t d[4];
                ldsm_x4(d, stg + b_off[0] + kb4);
                b[0][0] = d[0]; b[0][1] = d[1]; b[1][0] = d[2]; b[1][1] = d[3];
                ldsm_x4(d, stg + b_off[1] + kb4);
                b[2][0] = d[0]; b[2][1] = d[1]; b[3][0] = d[2]; b[3][1] = d[3];
            }
#pragma unroll
            for (int i = 0; i < 4; i++)
#pragma unroll
                for (int j = 0; j < 4; j++)
                    mma_f16(acc[i][j], a[i], b[j]);
        }
    }

    if (packout) {
        uint32_t* C = (uint32_t*)Cout;
        const int Nw = N / 2;
#pragma unroll
        for (int j = 0; j < 4; j++) {
            int n = n0 + wn * 32 + j * 8 + tig * 2;
            float2 bb = *(const float2*)(bias + n);
#pragma unroll
            for (int i = 0; i < 4; i++) {
                int m = m0 + wm * 64 + i * 16 + gid;
                C[(size_t)m * Nw + n / 2] =
                    h2(acc[i][j][0] + bb.x, acc[i][j][1] + bb.y);
                C[(size_t)(m + 8) * Nw + n / 2] =
                    h2(acc[i][j][2] + bb.x, acc[i][j][3] + bb.y);
            }
        }
    } else {
        float* C = (float*)Cout;
#pragma unroll
        for (int j = 0; j < 4; j++) {
            int n = n0 + wn * 32 + j * 8 + tig * 2;
            float2 bb = *(const float2*)(bias + n);
#pragma unroll
            for (int i = 0; i < 4; i++) {
                int m = m0 + wm * 64 + i * 16 + gid;
                *(float2*)(C + (size_t)m * N + n) =
                    make_float2(acc[i][j][0] + bb.x, acc[i][j][1] + bb.y);
                *(float2*)(C + (size_t)(m + 8) * N + n) =
                    make_float2(acc[i][j][2] + bb.x, acc[i][j][3] + bb.y);
            }
        }
    }
}

// ---------------- banded sliding-window attention, fp16 + hybrid exp2 -------
static __device__ __forceinline__ void swa_load_kv(
    int b, int hh, int ks, uint32_t* sw, int pb, int t)
{
    {
        const int kr = t >> 2, kc = (t & 3) * 8;
        const uint32_t* kp = g_qkvh + (size_t)(b * S_LEN + ks + kr) * QKV_W + hh * 96 + 32 + kc;
        uint32_t* kd = sw + KB_OFF + pb * (64 * KSTR) + kr * KSTR + kc;
        *(uint4*)kd       = *(const uint4*)kp;
        *(uint4*)(kd + 4) = *(const uint4*)(kp + 4);
    }
    {
        const int kr2 = t & 31, dg = t >> 5;
        const uint32_t* va = g_qkvh + (size_t)(b * S_LEN + ks + 2 * kr2) * QKV_W + hh * 96 + 64 + dg * 4;
        uint4 wa = *(const uint4*)va;
        uint4 wb = *(const uint4*)(va + QKV_W);
        uint32_t* vd = sw + VB_OFF + pb * (64 * VSTR) + kr2;
        uint32_t aw[4] = {wa.x, wa.y, wa.z, wa.w};
        uint32_t bw[4] = {wb.x, wb.y, wb.z, wb.w};
#pragma unroll
        for (int j = 0; j < 4; j++) {
            int d0 = dg * 8 + 2 * j;
            vd[(size_t)d0 * VSTR]       = __byte_perm(aw[j], bw[j], 0x5410);
            vd[(size_t)(d0 + 1) * VSTR] = __byte_perm(aw[j], bw[j], 0x7632);
        }
    }
}

__global__ __launch_bounds__(256, 2) void swa_mma(void)
{
    extern __shared__ uint32_t sw[];
    const int t = threadIdx.x;
    const int lane = t & 31, w = t >> 5;
    const int gid = lane >> 2, tig = lane & 3;
    const int nqc = S_LEN / AQT;
    const int qc = blockIdx.x % nqc;
    const int hh = (blockIdx.x / nqc) % NH;
    const int b  = blockIdx.x / (nqc * NH);
    const int qi0 = qc * AQT;

    {
        int r = t >> 1, c0 = (t & 1) * 16;
        const uint32_t* qp = g_qkvh + (size_t)(b * S_LEN + qi0 + r) * QKV_W + hh * 96 + c0;
        uint32_t* qs = sw + QS_OFF + r * QSTR + c0;
        *(uint4*)qs        = *(const uint4*)qp;
        *(uint4*)(qs + 4)  = *(const uint4*)(qp + 4);
        *(uint4*)(qs + 8)  = *(const uint4*)(qp + 8);
        *(uint4*)(qs + 12) = *(const uint4*)(qp + 12);
    }

    const int kt_lo = (qi0 < WRAD) ? (WRAD - qi0) / AKT : 0;
    const int kt_hi = min(ATILES - 1, (S_LEN + WRAD - AKT - qi0) / AKT);

    float oacc[8][4];
#pragma unroll
    for (int nj = 0; nj < 8; nj++)
#pragma unroll
        for (int e = 0; e < 4; e++) oacc[nj][e] = 0.f;
    float m[2] = {-1e30f, -1e30f};     // log2-domain running max
    float lp[2] = {0.f, 0.f};

    const int row0 = qi0 + w * 16 + gid;
    const uint32_t* qbase = sw + QS_OFF + (w * 16 + gid) * QSTR;

    swa_load_kv(b, hh, qi0 - WRAD + kt_lo * AKT, sw, 0, t);
    int pb = 0;

    for (int kt = kt_lo; kt <= kt_hi; kt++) {
        const int ks = qi0 - WRAD + kt * AKT;
        const bool pf = (kt < kt_hi);
        __syncthreads();

        const uint32_t* Kb = sw + KB_OFF + pb * (64 * KSTR);
        const uint32_t* Vb = sw + VB_OFF + pb * (64 * VSTR);

        float sacc[8][4];
#pragma unroll
        for (int nj = 0; nj < 8; nj++)
#pragma unroll
            for (int e = 0; e < 4; e++) sacc[nj][e] = 0.f;

#pragma unroll
        for (int c = 0; c < 4; c++) {
            uint32_t a[4];
            a[0] = qbase[c * 8 + tig];
            a[1] = qbase[8 * QSTR + c * 8 + tig];
            a[2] = qbase[c * 8 + tig + 4];
            a[3] = qbase[8 * QSTR + c * 8 + tig + 4];
#pragma unroll
            for (int nj = 0; nj < 8; nj++) {
                const uint32_t* krow = Kb + (nj * 8 + gid) * KSTR + c * 8;
                uint32_t bfr[2] = {krow[tig], krow[tig + 4]};
                mma_f16(sacc[nj], a, bfr);
            }
        }

        if (pf) {
            const uint32_t* np = g_qkvh +
                (size_t)(b * S_LEN + ks + AKT + (t >> 2)) * QKV_W + hh * 96 + 32 + (t & 3) * 16;
            prefetch_l2(np);
        }

        // ---- mask + scale (log2 domain) + warp-local online softmax ----
        float mt[2] = {-1e30f, -1e30f};
#pragma unroll
        for (int nj = 0; nj < 8; nj++)
#pragma unroll
            for (int e = 0; e < 4; e++) {
                int col = ks + nj * 8 + 2 * tig + (e & 1);
                int d = col - (row0 + (e >> 1) * 8);
                bool val = (d >= -WRAD) && (d <= WRAD);
                float sv = val ? sacc[nj][e] * SCALE_LOG2E : -1e30f;
                sacc[nj][e] = sv;
                mt[e >> 1] = fmaxf(mt[e >> 1], sv);
            }
#pragma unroll
        for (int hE = 0; hE < 2; hE++) {
            mt[hE] = fmaxf(mt[hE], __shfl_xor_sync(0xffffffffu, mt[hE], 1));
            mt[hE] = fmaxf(mt[hE], __shfl_xor_sync(0xffffffffu, mt[hE], 2));
            float mn = fmaxf(m[hE], mt[hE]);
            float corr = exp2f(m[hE] - mn);
            m[hE] = mn;
            lp[hE] *= corr;
#pragma unroll
            for (int nj = 0; nj < 8; nj++) {
                oacc[nj][2 * hE]     *= corr;
                oacc[nj][2 * hE + 1] *= corr;
            }
        }

        // exp2 hybrid: even nj -> MUFU exp2f, odd nj -> FMA-pipe fast_exp2
        uint32_t pw[8][2];
#pragma unroll
        for (int nj = 0; nj < 8; nj++) {
            float p[4];
#pragma unroll
            for (int e = 0; e < 4; e++) {
                float f = sacc[nj][e] - m[e >> 1];
                float pe = (nj & 1) ? fast_exp2(f) : exp2f(f);
                p[e] = (sacc[nj][e] > -1e29f) ? pe : 0.f;
                lp[e >> 1] += p[e];
            }
            pw[nj][0] = h2(p[0], p[1]);
            pw[nj][1] = h2(p[2], p[3]);
        }

        // ---- O += P @ V ----
#pragma unroll
        for (int c = 0; c < 4; c++) {
            uint32_t a[4] = {pw[2 * c][0], pw[2 * c][1], pw[2 * c + 1][0], pw[2 * c + 1][1]};
#pragma unroll
            for (int nj = 0; nj < 8; nj++) {
                const uint32_t* vrow = Vb + (nj * 8 + gid) * VSTR + c * 8;
                uint32_t bfr[2] = {vrow[tig], vrow[tig + 4]};
                mma_f16(oacc[nj], a, bfr);
            }
        }

        if (pf) {
            swa_load_kv(b, hh, ks + AKT, sw, pb ^ 1, t);
            pb ^= 1;
        }
    }

    float linv[2];
#pragma unroll
    for (int hE = 0; hE < 2; hE++) {
        float l = lp[hE];
        l += __shfl_xor_sync(0xffffffffu, l, 1);
        l += __shfl_xor_sync(0xffffffffu, l, 2);
        linv[hE] = 1.0f / l;
    }
    uint32_t* cp0 = g_ctxh + (size_t)(b * S_LEN + row0) * (EMB / 2) + hh * 32;
#pragma unroll
    for (int nj = 0; nj < 8; nj++) {
        cp0[nj * 4 + tig] = h2(oacc[nj][0] * linv[0], oacc[nj][1] * linv[0]);
        cp0[(size_t)8 * (EMB / 2) + nj * 4 + tig] =
            h2(oacc[nj][2] * linv[1], oacc[nj][3] * linv[1]);
    }
}

// ---------------- launch ----------------------------------------------------
extern "C" void kernel_launch(void* const* d_in, const int* in_sizes, int n_in,
                              void* d_out, int out_size) {
    const float* x    = (const float*)d_in[0];
    const float* Wqkv = (const float*)d_in[1];
    const float* bqkv = (const float*)d_in[2];
    const float* Wo   = (const float*)d_in[3];
    const float* bo   = (const float*)d_in[4];
    float* out = (float*)d_out;

    uint32_t *qkvh, *ctxh, *xh, *wqt, *wot;
    cudaGetSymbolAddress((void**)&qkvh, g_qkvh);
    cudaGetSymbolAddress((void**)&ctxh, g_ctxh);
    cudaGetSymbolAddress((void**)&xh,   g_xh);
    cudaGetSymbolAddress((void**)&wqt,  g_wqt);
    cudaGetSymbolAddress((void**)&wot,  g_wot);

    const int M = BATCH * S_LEN;   // 8192

    cudaFuncSetAttribute(gemm_fp16, cudaFuncAttributeMaxDynamicSharedMemorySize, GEMM_SMEM);
    cudaFuncSetAttribute(swa_mma, cudaFuncAttributeMaxDynamicSharedMemorySize, ASMEM);

    pack_a_fp16<<<(M * EMB) / (256 * 8), 256>>>(x, xh);
    pack_bt_fp16<<<dim3(QKV_N / 32, (EMB / 2) / 8), 256>>>(Wqkv, wqt, QKV_N, EMB);
    pack_bt_fp16<<<dim3(EMB / 32, (EMB / 2) / 8), 256>>>(Wo, wot, EMB, EMB);

    gemm_fp16<<<dim3(QKV_N / BN, M / BM), 256, GEMM_SMEM>>>(
        xh, wqt, bqkv, qkvh, M, QKV_N, EMB, 1);

    swa_mma<<<BATCH * NH * (S_LEN / AQT), 256, ASMEM>>>();

    gemm_fp16<<<dim3(EMB / BN, M / BM), 256, GEMM_SMEM>>>(
        ctxh, wot, bo, out, M, EMB, EMB, 0);
}